// round 15
// baseline (speedup 1.0000x reference)
#include <cuda_runtime.h>
#include <cuda_fp16.h>
#include <math.h>

#define N_NODES 50000
#define D 100
#define DH 128      // half-slots per node row: 100 fp16 premult feats, w(fp32)@100-101, 0@102-103
#define E_EDGES 800000
#define OUTD 300

// Scratch (allocation-free). Row c of g_h[b] (256B, line-aligned):
//   halves 0..99 = fp16(w_c * f_c[j]);  halves 100..101 = w_c as fp32 bits; 102..103 = 0.
// w = exp(score), score in [-1,1] so exp never overflows and the reference's
// max-subtraction cancels exactly in the softmax ratio.
__device__ __align__(256) __half g_h[2][(size_t)N_NODES * DH];
__device__ __align__(16) float g_nr[128];
__device__ __align__(16) int g_coff[E_EDGES + 32];   // col * 256 (byte offset)
__device__ int g_rowptr[N_NODES + 1];

typedef unsigned long long u64;

// ---------------------------------------------------------------------------
__device__ __forceinline__ void fadd2(u64& a, u64 b) {
    asm("add.rn.f32x2 %0, %0, %1;" : "+l"(a) : "l"(b));
}
__device__ __forceinline__ float2 unpack2(u64 v) {
    float2 r;
    asm("mov.b64 {%0, %1}, %2;" : "=f"(r.x), "=f"(r.y) : "l"(v));
    return r;
}
__device__ __forceinline__ u64 pack2(float x, float y) {
    u64 r;
    asm("mov.b64 %0, {%1, %2};" : "=l"(r) : "f"(x), "f"(y));
    return r;
}
__device__ __forceinline__ void hacc(unsigned int& a, unsigned int b) { // half2 +=
    __half2 ha = *(__half2*)&a;
    __half2 hb = *(__half2*)&b;
    ha = __hadd2(ha, hb);
    a = *(unsigned int*)&ha;
}
__device__ __forceinline__ float tanha(float x) {      // HW tanh approx
    float r;
    asm("tanh.approx.f32 %0, %1;" : "=f"(r) : "f"(x));
    return r;
}

// ---------------------------------------------------------------------------
// Prep: packed col byte-offsets + CSR row pointers (rows sorted; binary search).
// Block 0 threads 0..127 additionally build the normalized none_relation.
__global__ void prep_kernel(const int* __restrict__ adj,
                            const float* __restrict__ none_rel) {
    if (blockIdx.x == 0 && threadIdx.x < 128) {
        __shared__ float ssum[128];
        int t = threadIdx.x;
        float v = (t < D) ? none_rel[t] : 0.f;
        ssum[t] = v * v;
        __syncthreads();
        for (int s = 64; s > 0; s >>= 1) {
            if (t < s) ssum[t] += ssum[t + s];
            __syncthreads();
        }
        float inv = 1.f / fmaxf(sqrtf(ssum[0]), 1e-12f);
        g_nr[t] = (t < D) ? v * inv : 0.f;
    }
    int i = blockIdx.x * blockDim.x + threadIdx.x;
    if (i < E_EDGES)
        g_coff[i] = adj[2 * i + 1] << 8;   // col * 256 bytes
    if (i <= N_NODES) {
        int lo = 0, hi = E_EDGES;
        while (lo < hi) {
            int mid = (lo + hi) >> 1;
            if (adj[2 * mid] < i) lo = mid + 1; else hi = mid;
        }
        g_rowptr[i] = lo;
    }
}

// ---------------------------------------------------------------------------
// Warp-collective epilogue: r = fp32 feature chunk f[4l..4l+3] on lanes 0..24.
// w = exp(-dot(l2norm(f), nr)). Store fp16 premult row, fp32 w, zero pad.
__device__ __forceinline__ void epilogue_store(float4 r, int lane, int node, int fbuf) {
    float dot = 0.f, ss = 0.f;
    if (lane < 25) {
        float4 nv = *(const float4*)(g_nr + lane * 4);
        dot = r.x * nv.x + r.y * nv.y + r.z * nv.z + r.w * nv.w;
        ss  = r.x * r.x + r.y * r.y + r.z * r.z + r.w * r.w;
    }
    #pragma unroll
    for (int o = 16; o; o >>= 1) {
        dot += __shfl_xor_sync(0xffffffffu, dot, o);
        ss  += __shfl_xor_sync(0xffffffffu, ss, o);
    }
    float w = __expf(-dot / fmaxf(sqrtf(ss), 1e-12f));
    __half* row = g_h[fbuf] + ((size_t)node << 7);
    if (lane < 25) {
        __half2 p0 = __floats2half2_rn(w * r.x, w * r.y);
        __half2 p1 = __floats2half2_rn(w * r.z, w * r.w);
        uint2 u;
        u.x = *(unsigned int*)&p0;
        u.y = *(unsigned int*)&p1;
        *(uint2*)(row + lane * 4) = u;
    } else if (lane == 25) {
        uint2 u;
        u.x = __float_as_uint(w);   // halves 100..101
        u.y = 0u;                   // halves 102..103 MUST be zero (lane 12 adds them)
        *(uint2*)(row + 100) = u;
    }
}

// ---------------------------------------------------------------------------
// Layer 0: r = tanh(features); write out cols [0,D), build g_h[0].
__global__ void tanh_score_kernel(const float* __restrict__ feat,
                                  float* __restrict__ out) {
    int node = (blockIdx.x * blockDim.x + threadIdx.x) >> 5;
    int lane = threadIdx.x & 31;
    if (node >= N_NODES) return;
    float4 r = make_float4(0.f, 0.f, 0.f, 0.f);
    if (lane < 25) {
        float4 v = *(const float4*)(feat + (size_t)node * D + lane * 4);
        r.x = tanha(v.x); r.y = tanha(v.y); r.z = tanha(v.z); r.w = tanha(v.w);
        *(float4*)(out + (size_t)node * OUTD + lane * 4) = r;
    }
    epilogue_store(r, lane, node, 0);
}

// ---------------------------------------------------------------------------
// Attention row kernel: fp16 gather-sum with HADD2 accumulation.
// Lanes 0..12 each load 16B (8 halves). Lane 12's .z word = fp32 w -> den.
// fp16 chains flushed to packed-fp32 accumulators every <=7 edges.
template <bool LAST>
__global__ void __launch_bounds__(128) row_kernel(int buf, float* __restrict__ out,
                                                  int outoff) {
    int row = (blockIdx.x * blockDim.x + threadIdx.x) >> 5;
    int lane = threadIdx.x & 31;
    if (row >= N_NODES) return;
    int beg = g_rowptr[row];
    int end = g_rowptr[row + 1];
    const char* __restrict__ hb = (const char*)g_h[buf];
    bool act = (lane < 13);
    bool wl = (lane == 12);
    int laneoff = lane * 16;

    u64 a0 = 0ull, a1 = 0ull, a2 = 0ull, a3 = 0ull;   // fp32 f32x2 accumulators
    unsigned int h0 = 0u, h1 = 0u, h2 = 0u, h3 = 0u;  // half2 accumulators
    float den = 0.f;                                   // valid on lane 12

#define EDGE(off) do {                                                        \
        if (act) {                                                            \
            uint4 v = *(const uint4*)(hb + (off) + laneoff);                  \
            hacc(h0, v.x);                                                    \
            hacc(h1, v.y);                                                    \
            if (wl) den += __uint_as_float(v.z); else hacc(h2, v.z);          \
            hacc(h3, v.w);  /* lane12: halves 102..103 are zero */            \
        } } while (0)
#define FLUSH() do {                                                          \
        float2 f0 = __half22float2(*(__half2*)&h0);                           \
        float2 f1 = __half22float2(*(__half2*)&h1);                           \
        float2 f2 = __half22float2(*(__half2*)&h2);                           \
        float2 f3 = __half22float2(*(__half2*)&h3);                           \
        fadd2(a0, pack2(f0.x, f0.y)); fadd2(a1, pack2(f1.x, f1.y));           \
        fadd2(a2, pack2(f2.x, f2.y)); fadd2(a3, pack2(f3.x, f3.y));           \
        h0 = h1 = h2 = h3 = 0u;                                               \
    } while (0)

    int e = beg;
    // Peel to int4-aligned coff reads, then flush (bounds chain length).
    int pre = (4 - (beg & 3)) & 3;
    if (pre > end - beg) pre = end - beg;
    for (int k = 0; k < pre; ++k, ++e) EDGE(g_coff[e]);
    if (pre) FLUSH();

    for (; e + 4 <= end; e += 4) {
        int4 q = *(const int4*)(g_coff + e);
        EDGE(q.x); EDGE(q.y); EDGE(q.z); EDGE(q.w);
        FLUSH();
    }
    for (; e < end; ++e) EDGE(g_coff[e]);
    FLUSH();
#undef EDGE
#undef FLUSH

    den = __shfl_sync(0xffffffffu, den, 12);
    float inv = (end > beg) ? (1.f / den) : 0.f;

    // Redistribute: lane t (0..24) wants f[4t..4t+3]; source lane s = t>>1
    // holds f[8s..8s+7] in (a0,a1,a2,a3). Even t -> (a0,a1); odd t -> (a2,a3).
    int src = lane >> 1;
    u64 b0 = __shfl_sync(0xffffffffu, a0, src);
    u64 b1 = __shfl_sync(0xffffffffu, a1, src);
    u64 b2 = __shfl_sync(0xffffffffu, a2, src);
    u64 b3 = __shfl_sync(0xffffffffu, a3, src);
    u64 plo = (lane & 1) ? b2 : b0;
    u64 phi = (lane & 1) ? b3 : b1;
    float2 fl = unpack2(plo);
    float2 fh = unpack2(phi);

    float4 r;
    r.x = tanha(fl.x * inv);
    r.y = tanha(fl.y * inv);
    r.z = tanha(fh.x * inv);
    r.w = tanha(fh.y * inv);
    if (lane < 25)
        *(float4*)(out + (size_t)row * OUTD + outoff + lane * 4) = r;
    if (!LAST)
        epilogue_store(r, lane, row, buf ^ 1);
}

// ---------------------------------------------------------------------------
extern "C" void kernel_launch(void* const* d_in, const int* in_sizes, int n_in,
                              void* d_out, int out_size) {
    const float* features = (const float*)d_in[0];
    // d_in[1] = rel_emb: unused by the reference computation.
    const int* adj        = (const int*)d_in[2];   // int32 pairs (JAX demotes int64)
    const float* none_rel = (const float*)d_in[3];
    float* out = (float*)d_out;

    prep_kernel<<<(E_EDGES + 255) / 256, 256>>>(adj, none_rel);
    tanh_score_kernel<<<(N_NODES * 32 + 255) / 256, 256>>>(features, out);
    const int RB = (N_NODES * 32 + 127) / 128;
    row_kernel<false><<<RB, 128>>>(0, out, D);
    row_kernel<true ><<<RB, 128>>>(1, out, 2 * D);
}